// round 6
// baseline (speedup 1.0000x reference)
#include <cuda_runtime.h>
#include <cuda_bf16.h>

#define NB    16
#define LSEQ  1024
#define DH    512
#define NCLS  64
#define NROWS (NB * LSEQ)

// ---------------- scratch (static device memory; no allocations) -------------
__device__ float    g_XS[NROWS * DH];   // input projection for current layer, rows r = t*16 + b
__device__ float    g_O0[NROWS * DH];   // layer-0 outputs
__device__ float    g_O1[NROWS * DH];   // layer-1 outputs
__device__ float    g_hbuf[2 * NB * DH];
__device__ unsigned g_ctr[NB];

// ---------------- init: reset recurrence state -------------------------------
__global__ void init_kernel() {
  int i = blockIdx.x * blockDim.x + threadIdx.x;
  if (i < 2 * NB * DH) g_hbuf[i] = 0.0f;
  if (i < NB)          g_ctr[i]  = 0u;
}

// ---------------- GEMM: g_XS = A @ W^T + bias1 + bias2 -----------------------
// mode 0: A row r = emb[x[b][t]]   (r = t*16 + b)
// mode 1: A row r = g_O0[r]
// Tile 128x128, K-chunk 16, 8x8 microtile per thread (256 threads).
__global__ __launch_bounds__(256) void gemm_kernel(
    int mode,
    const int*   __restrict__ xtok,
    const float* __restrict__ emb,
    const float* __restrict__ W,        // [DH][DH], C[r][h] = sum_d A[r][d]*W[h][d]
    const float* __restrict__ bias1,
    const float* __restrict__ bias2)
{
  __shared__ float As[16][132];
  __shared__ float Bs[16][132];
  const int r0  = blockIdx.x * 128;
  const int h0  = blockIdx.y * 128;
  const int tid = threadIdx.x;
  const int tr  = (tid & 15) * 8;
  const int tc  = (tid >> 4) * 8;

  float acc[8][8];
#pragma unroll
  for (int i = 0; i < 8; i++)
#pragma unroll
    for (int j = 0; j < 8; j++) acc[i][j] = 0.0f;

  for (int kk = 0; kk < DH; kk += 16) {
#pragma unroll
    for (int it = 0; it < 2; it++) {
      int idx = tid + it * 256;        // 0..511
      int i = idx >> 2;                // row within tile 0..127
      int q = idx & 3;                 // k-quad
      const float* arow;
      if (mode == 0) {
        int r = r0 + i;
        int tok = xtok[(r & 15) * LSEQ + (r >> 4)];
        arow = emb + (size_t)tok * DH;
      } else {
        arow = g_O0 + (size_t)(r0 + i) * DH;
      }
      float4 va = *(const float4*)(arow + kk + q * 4);
      As[q * 4 + 0][i] = va.x; As[q * 4 + 1][i] = va.y;
      As[q * 4 + 2][i] = va.z; As[q * 4 + 3][i] = va.w;
      float4 vb = *(const float4*)(W + (size_t)(h0 + i) * DH + kk + q * 4);
      Bs[q * 4 + 0][i] = vb.x; Bs[q * 4 + 1][i] = vb.y;
      Bs[q * 4 + 2][i] = vb.z; Bs[q * 4 + 3][i] = vb.w;
    }
    __syncthreads();
#pragma unroll
    for (int k = 0; k < 16; k++) {
      float a[8], bb[8];
      *(float4*)&a[0]  = *(const float4*)&As[k][tr];
      *(float4*)&a[4]  = *(const float4*)&As[k][tr + 4];
      *(float4*)&bb[0] = *(const float4*)&Bs[k][tc];
      *(float4*)&bb[4] = *(const float4*)&Bs[k][tc + 4];
#pragma unroll
      for (int i = 0; i < 8; i++)
#pragma unroll
        for (int j = 0; j < 8; j++) acc[i][j] += a[i] * bb[j];
    }
    __syncthreads();
  }

  float bs[8];
#pragma unroll
  for (int j = 0; j < 8; j++) bs[j] = bias1[h0 + tc + j] + bias2[h0 + tc + j];
#pragma unroll
  for (int i = 0; i < 8; i++) {
    float* crow = g_XS + (size_t)(r0 + tr + i) * DH + h0 + tc;
#pragma unroll
    for (int j = 0; j < 8; j++) crow[j] = acc[i][j] + bs[j];
  }
}

// ---------------- recurrence ------------------------------------------------
__device__ __forceinline__ unsigned ld_acq(const unsigned* p) {
  unsigned v;
  asm volatile("ld.acquire.gpu.global.u32 %0, [%1];" : "=r"(v) : "l"(p) : "memory");
  return v;
}

// 128 CTAs: group g = blockIdx/8 = batch element, 8 CTAs per group each owning
// 64 output dims. Wh slice register-resident. h exchanged through L2 with an
// atomic generation counter per group (all 128 CTAs co-resident: 128 < 148 SMs,
// 1 CTA/SM at 512 threads).
__global__ __launch_bounds__(512, 1) void rnn_kernel(const float* __restrict__ Wh, int layer)
{
  const int g    = blockIdx.x >> 3;
  const int sub  = blockIdx.x & 7;
  const int co   = sub * 64;
  const int tid  = threadIdx.x;
  const int lane = tid & 31;
  const int w    = tid >> 5;            // 0..15, warp owns outputs co+4w..co+4w+3
  float* outp    = layer ? g_O1 : g_O0;
  unsigned* ctr  = &g_ctr[g];

  // load weight slice: lane covers dims d = lane + 32k
  float wreg[64];
#pragma unroll
  for (int j = 0; j < 4; j++)
#pragma unroll
    for (int k = 0; k < 16; k++)
      wreg[j * 16 + k] = Wh[(size_t)(co + w * 4 + j) * DH + lane + 32 * k];

  const int o_lane = co + w * 4 + (lane & 3);

#pragma unroll 1
  for (int t = 0; t < LSEQ; t++) {
    // prefetch xs (independent of h_{t-1})
    float xsv = 0.0f;
    if (lane < 4) xsv = __ldg(&g_XS[(size_t)(t * NB + g) * DH + o_lane]);

    // wait until all 8 CTAs of the group produced h_{t-1}
    if (tid == 0) {
      unsigned tgt = 8u * (unsigned)t;
      while (ld_acq(ctr) < tgt) {}
    }
    __syncthreads();

    const float* hprev = &g_hbuf[((t + 1) & 1) * NB * DH + g * DH];
    float hr[16];
#pragma unroll
    for (int k = 0; k < 16; k++) hr[k] = __ldcg(hprev + lane + 32 * k);

    float a0 = 0.f, a1 = 0.f, a2 = 0.f, a3 = 0.f;
#pragma unroll
    for (int k = 0; k < 16; k++) {
      a0 += wreg[0 * 16 + k] * hr[k];
      a1 += wreg[1 * 16 + k] * hr[k];
      a2 += wreg[2 * 16 + k] * hr[k];
      a3 += wreg[3 * 16 + k] * hr[k];
    }
#pragma unroll
    for (int off = 16; off; off >>= 1) {
      a0 += __shfl_xor_sync(0xffffffffu, a0, off);
      a1 += __shfl_xor_sync(0xffffffffu, a1, off);
      a2 += __shfl_xor_sync(0xffffffffu, a2, off);
      a3 += __shfl_xor_sync(0xffffffffu, a3, off);
    }

    if (lane < 4) {
      float y = (lane == 0) ? a0 : (lane == 1) ? a1 : (lane == 2) ? a2 : a3;
      float v = tanhf(y + xsv);
      outp[(size_t)(t * NB + g) * DH + o_lane] = v;
      __stcg(&g_hbuf[(t & 1) * NB * DH + g * DH + o_lane], v);
      __threadfence();                   // make h_t visible GPU-wide before arrive
    }
    __syncthreads();
    if (tid == 0) atomicAdd(ctr, 1u);
  }
}

// ---------------- attention (eos row only) + decoder -------------------------
__global__ __launch_bounds__(256) void attn_kernel(
    const int*   __restrict__ eos,
    const float* __restrict__ Wc, const float* __restrict__ bc,
    const float* __restrict__ Wd, const float* __restrict__ bd,
    float* __restrict__ out)
{
  __shared__ float sq[DH];
  __shared__ float sp[LSEQ];
  __shared__ float az[DH];
  __shared__ float sd[DH];
  __shared__ float sred[8];

  const int b    = blockIdx.x;
  const int e    = eos[b];
  const int tid  = threadIdx.x;
  const int lane = tid & 31;
  const int w    = tid >> 5;             // 8 warps

  for (int i = tid; i < DH; i += 256) sq[i] = g_O1[(size_t)(e * NB + b) * DH + i];
  __syncthreads();

  // scores (strict-causal mask: s >= e -> -1e9 exactly, as in reference)
  for (int s = w; s < LSEQ; s += 8) {
    const float* row = &g_O1[(size_t)(s * NB + b) * DH];
    float acc = 0.0f;
#pragma unroll
    for (int m = 0; m < 4; m++) {
      int k = lane * 4 + 128 * m;
      float4 v = *(const float4*)(row + k);
      acc += v.x * sq[k] + v.y * sq[k + 1] + v.z * sq[k + 2] + v.w * sq[k + 3];
    }
#pragma unroll
    for (int off = 16; off; off >>= 1) acc += __shfl_xor_sync(0xffffffffu, acc, off);
    if (lane == 0) sp[s] = (s < e) ? acc : -1.0e9f;
  }
  __syncthreads();

  // softmax over all 1024 entries (matches jax exactly, incl. eos==0 uniform case)
  float mx = -3.4e38f;
  for (int s = tid; s < LSEQ; s += 256) mx = fmaxf(mx, sp[s]);
#pragma unroll
  for (int off = 16; off; off >>= 1) mx = fmaxf(mx, __shfl_xor_sync(0xffffffffu, mx, off));
  if (lane == 0) sred[w] = mx;
  __syncthreads();
  mx = sred[0];
#pragma unroll
  for (int i = 1; i < 8; i++) mx = fmaxf(mx, sred[i]);
  __syncthreads();

  float ps = 0.0f;
  for (int s = tid; s < LSEQ; s += 256) {
    float e2 = expf(sp[s] - mx);
    sp[s] = e2;
    ps += e2;
  }
#pragma unroll
  for (int off = 16; off; off >>= 1) ps += __shfl_xor_sync(0xffffffffu, ps, off);
  if (lane == 0) sred[w] = ps;
  __syncthreads();
  float S = sred[0];
#pragma unroll
  for (int i = 1; i < 8; i++) S += sred[i];
  const float inv = 1.0f / S;
  __syncthreads();

  // att_z = sum_s p[s] * out1[b][s][:]
  for (int h = tid; h < DH; h += 256) {
    float acc = 0.0f;
    const float* col = &g_O1[(size_t)b * DH + h];
#pragma unroll 4
    for (int s = 0; s < LSEQ; s++) acc += sp[s] * col[(size_t)s * NB * DH];
    az[h] = acc * inv;
  }
  __syncthreads();

  // dec_in[j] = bc[j] + Wc[j][0:512].az + Wc[j][512:1024].z(=sq)
  for (int j = w; j < DH; j += 8) {
    const float* wr = Wc + (size_t)j * 1024;
    float acc = 0.0f;
#pragma unroll
    for (int m = 0; m < 8; m++) {
      int k = lane * 4 + 128 * m;
      float4 v = *(const float4*)(wr + k);
      const float* src = (m < 4) ? az : sq;
      int kk = (m < 4) ? k : (k - 512);
      acc += v.x * src[kk] + v.y * src[kk + 1] + v.z * src[kk + 2] + v.w * src[kk + 3];
    }
#pragma unroll
    for (int off = 16; off; off >>= 1) acc += __shfl_xor_sync(0xffffffffu, acc, off);
    if (lane == 0) sd[j] = acc + bc[j];
  }
  __syncthreads();

  // logits
  for (int c = w; c < NCLS; c += 8) {
    const float* wr = Wd + (size_t)c * DH;
    float acc = 0.0f;
#pragma unroll
    for (int m = 0; m < 4; m++) {
      int k = lane * 4 + 128 * m;
      float4 v = *(const float4*)(wr + k);
      acc += v.x * sd[k] + v.y * sd[k + 1] + v.z * sd[k + 2] + v.w * sd[k + 3];
    }
#pragma unroll
    for (int off = 16; off; off >>= 1) acc += __shfl_xor_sync(0xffffffffu, acc, off);
    if (lane == 0) out[b * NCLS + c] = acc + bd[c];
  }
}

// ---------------- host ---------------------------------------------------------
extern "C" void kernel_launch(void* const* d_in, const int* in_sizes, int n_in,
                              void* d_out, int out_size) {
  const int*   x    = (const int*)  d_in[0];
  const int*   eos  = (const int*)  d_in[1];
  const float* emb  = (const float*)d_in[2];
  const float* W_ih = (const float*)d_in[3];   // [2][512][512]
  const float* W_hh = (const float*)d_in[4];   // [2][512][512]
  const float* b_ih = (const float*)d_in[5];   // [2][512]
  const float* b_hh = (const float*)d_in[6];   // [2][512]
  const float* Wc   = (const float*)d_in[7];   // [512][1024]
  const float* bc   = (const float*)d_in[8];
  const float* Wd   = (const float*)d_in[9];   // [64][512]
  const float* bd   = (const float*)d_in[10];
  float* out = (float*)d_out;

  dim3 ggrid(NROWS / 128, DH / 128);

  // layer 0
  init_kernel<<<64, 256>>>();
  gemm_kernel<<<ggrid, 256>>>(0, x, emb, W_ih, b_ih, b_hh);
  rnn_kernel<<<128, 512>>>(W_hh, 0);

  // layer 1
  init_kernel<<<64, 256>>>();
  gemm_kernel<<<ggrid, 256>>>(1, x, emb, W_ih + DH * DH, b_ih + DH, b_hh + DH);
  rnn_kernel<<<128, 512>>>(W_hh + DH * DH, 1);

  // attention + decoder
  attn_kernel<<<NB, 256>>>(eos, Wc, bc, Wd, bd, out);
}

// round 7
// speedup vs baseline: 1.5462x; 1.5462x over previous
#include <cuda_runtime.h>
#include <cuda_bf16.h>
#include <cstdint>

#define NB    16
#define LSEQ  1024
#define DH    512
#define NCLS  64
#define NROWS (NB * LSEQ)

// ---------------- scratch (static device memory; no allocations) -------------
__device__ float g_XS[NROWS * DH];   // input projection for current layer, rows r = t*16 + b
__device__ float g_O0[NROWS * DH];   // layer-0 outputs
__device__ float g_O1[NROWS * DH];   // layer-1 outputs

// ---------------- small helpers ----------------------------------------------
__device__ __forceinline__ uint32_t s2u(const void* p) {
  uint32_t a;
  asm("{ .reg .u64 t; cvta.to.shared.u64 t, %1; cvt.u32.u64 %0, t; }" : "=r"(a) : "l"(p));
  return a;
}
__device__ __forceinline__ unsigned long long pk2(float lo, float hi) {
  unsigned long long r;
  asm("mov.b64 %0, {%1, %2};" : "=l"(r) : "f"(lo), "f"(hi));
  return r;
}
__device__ __forceinline__ void upk2(float& lo, float& hi, unsigned long long v) {
  asm("mov.b64 {%0, %1}, %2;" : "=f"(lo), "=f"(hi) : "l"(v));
}
__device__ __forceinline__ void fma2(unsigned long long& d, unsigned long long a,
                                     unsigned long long b) {
  asm("fma.rn.f32x2 %0, %1, %2, %0;" : "+l"(d) : "l"(a), "l"(b));
}
__device__ __forceinline__ void mbar_init(uint32_t mbar, uint32_t cnt) {
  asm volatile("mbarrier.init.shared.b64 [%0], %1;" :: "r"(mbar), "r"(cnt) : "memory");
}
__device__ __forceinline__ void mbar_expect_tx(uint32_t mbar, uint32_t bytes) {
  asm volatile("mbarrier.arrive.expect_tx.shared.b64 _, [%0], %1;"
               :: "r"(mbar), "r"(bytes) : "memory");
}
__device__ __forceinline__ void mbar_wait_parity(uint32_t mbar, uint32_t parity) {
  asm volatile(
      "{\n\t.reg .pred P1;\n\t"
      "WAIT_LOOP_%=:\n\t"
      "mbarrier.try_wait.parity.acquire.cta.shared::cta.b64 P1, [%0], %1, 0x989680;\n\t"
      "@P1 bra.uni WAIT_DONE_%=;\n\t"
      "bra.uni WAIT_LOOP_%=;\n\t"
      "WAIT_DONE_%=:\n\t}"
      :: "r"(mbar), "r"(parity) : "memory");
}
__device__ __forceinline__ uint32_t mapa_u32(uint32_t addr, uint32_t rank) {
  uint32_t r;
  asm("mapa.shared::cluster.u32 %0, %1, %2;" : "=r"(r) : "r"(addr), "r"(rank));
  return r;
}
__device__ __forceinline__ void st_async_f32(uint32_t dst, float v, uint32_t mbar) {
  asm volatile(
      "st.async.shared::cluster.mbarrier::complete_tx::bytes.b32 [%0], %1, [%2];"
      :: "r"(dst), "f"(v), "r"(mbar) : "memory");
}

// ---------------- GEMM: g_XS = A @ W^T + bias1 + bias2 -----------------------
// mode 0: A row r = emb[x[b][t]]   (r = t*16 + b);   mode 1: A row r = g_O0[r]
// Tile 128x128, K-chunk 16, 8x8 microtile (256 threads), f32x2 packed FMA.
__global__ __launch_bounds__(256) void gemm_kernel(
    int mode, const int* __restrict__ xtok, const float* __restrict__ emb,
    const float* __restrict__ W, const float* __restrict__ bias1,
    const float* __restrict__ bias2)
{
  __shared__ __align__(16) float As[16][132];
  __shared__ __align__(16) float Bs[16][132];
  const int r0  = blockIdx.x * 128;
  const int h0  = blockIdx.y * 128;
  const int tid = threadIdx.x;
  const int tr  = (tid & 15) * 8;
  const int tc  = (tid >> 4) * 8;

  unsigned long long acc2[8][4];
#pragma unroll
  for (int i = 0; i < 8; i++)
#pragma unroll
    for (int j = 0; j < 4; j++) acc2[i][j] = 0ull;

  for (int kk = 0; kk < DH; kk += 16) {
#pragma unroll
    for (int it = 0; it < 2; it++) {
      int idx = tid + it * 256;        // 0..511
      int i = idx >> 2;                // row within tile 0..127
      int q = idx & 3;                 // k-quad
      const float* arow;
      if (mode == 0) {
        int r = r0 + i;
        int tok = xtok[(r & 15) * LSEQ + (r >> 4)];
        arow = emb + (size_t)tok * DH;
      } else {
        arow = g_O0 + (size_t)(r0 + i) * DH;
      }
      float4 va = *(const float4*)(arow + kk + q * 4);
      As[q * 4 + 0][i] = va.x; As[q * 4 + 1][i] = va.y;
      As[q * 4 + 2][i] = va.z; As[q * 4 + 3][i] = va.w;
      float4 vb = *(const float4*)(W + (size_t)(h0 + i) * DH + kk + q * 4);
      Bs[q * 4 + 0][i] = vb.x; Bs[q * 4 + 1][i] = vb.y;
      Bs[q * 4 + 2][i] = vb.z; Bs[q * 4 + 3][i] = vb.w;
    }
    __syncthreads();
#pragma unroll
    for (int k = 0; k < 16; k++) {
      float a[8];
      *(float4*)&a[0] = *(const float4*)&As[k][tr];
      *(float4*)&a[4] = *(const float4*)&As[k][tr + 4];
      const unsigned long long* brow = (const unsigned long long*)&Bs[k][tc];
      unsigned long long b2[4];
#pragma unroll
      for (int j = 0; j < 4; j++) b2[j] = brow[j];
#pragma unroll
      for (int i = 0; i < 8; i++) {
        unsigned long long a2 = pk2(a[i], a[i]);
#pragma unroll
        for (int j = 0; j < 4; j++) fma2(acc2[i][j], a2, b2[j]);
      }
    }
    __syncthreads();
  }

  float bs[8];
#pragma unroll
  for (int j = 0; j < 8; j++) bs[j] = bias1[h0 + tc + j] + bias2[h0 + tc + j];
#pragma unroll
  for (int i = 0; i < 8; i++) {
    float* crow = g_XS + (size_t)(r0 + tr + i) * DH + h0 + tc;
#pragma unroll
    for (int j = 0; j < 4; j++) {
      float lo, hi;
      upk2(lo, hi, acc2[i][j]);
      crow[2 * j]     = lo + bs[2 * j];
      crow[2 * j + 1] = hi + bs[2 * j + 1];
    }
  }
}

// ---------------- recurrence: 16 clusters of 8 CTAs, DSMEM h-exchange ---------
// Cluster = one batch element. CTA rank owns 64 output dims, Wh slice packed
// f32x2 register-resident. h exchanged via st.async into all 8 CTAs' SMEM with
// double-buffered mbarriers (expect_tx = 512 floats = 2048 B per phase).
__global__ void __launch_bounds__(512, 1) rnn_cluster_kernel(
    const float* __restrict__ Wh, int layer)
{
  __shared__ __align__(16) float hbuf[2][DH];
  __shared__ __align__(8) unsigned long long mbar[2];

  const int g    = blockIdx.x >> 3;
  const int tid  = threadIdx.x;
  const int lane = tid & 31;
  const int w    = tid >> 5;                 // 0..15
  uint32_t rank;
  asm("mov.u32 %0, %%cluster_ctarank;" : "=r"(rank));
  const int co = (int)rank * 64;
  float* outp = layer ? g_O1 : g_O0;

  const uint32_t hb_addr = s2u(&hbuf[0][0]);
  const uint32_t mb_addr = s2u(&mbar[0]);
  const uint32_t mb_delta = mb_addr - hb_addr;

  // packed weight slice: outputs co+4w+j, pair m covers dims (lane+64m, lane+64m+32)
  unsigned long long wp0[8], wp1[8], wp2[8], wp3[8];
  {
    const float* wr0 = Wh + (size_t)(co + w * 4 + 0) * DH + lane;
    const float* wr1 = Wh + (size_t)(co + w * 4 + 1) * DH + lane;
    const float* wr2 = Wh + (size_t)(co + w * 4 + 2) * DH + lane;
    const float* wr3 = Wh + (size_t)(co + w * 4 + 3) * DH + lane;
#pragma unroll
    for (int m = 0; m < 8; m++) {
      wp0[m] = pk2(wr0[64 * m], wr0[64 * m + 32]);
      wp1[m] = pk2(wr1[64 * m], wr1[64 * m + 32]);
      wp2[m] = pk2(wr2[64 * m], wr2[64 * m + 32]);
      wp3[m] = pk2(wr3[64 * m], wr3[64 * m + 32]);
    }
  }

  // peer SMEM bases (compile-time-indexed array -> stays in registers)
  uint32_t peer_hb[8];
#pragma unroll
  for (int r = 0; r < 8; r++) peer_hb[r] = mapa_u32(hb_addr, (uint32_t)r);

  if (tid == 0) {
    mbar_init(mb_addr, 1);
    mbar_init(mb_addr + 8, 1);
    mbar_expect_tx(mb_addr + 8, 2048);       // arm buffer 1 for step-0 exchange
  }
  for (int i = tid; i < DH; i += 512) hbuf[0][i] = 0.0f;   // h_{-1} = 0
  asm volatile("barrier.cluster.arrive.aligned;" ::: "memory");
  asm volatile("barrier.cluster.wait.aligned;" ::: "memory");

  const int o = co + w * 4 + (lane & 3);

#pragma unroll 1
  for (int t = 0; t < LSEQ; t++) {
    const int cb = t & 1, nb = cb ^ 1;

    // prefetch xs (independent of h_{t-1}) before blocking
    float xsv = 0.0f;
    if (lane < 4) xsv = __ldg(&g_XS[(size_t)(t * NB + g) * DH + o]);

    if (t > 0) {
      if (tid == 0) mbar_expect_tx(mb_addr + (uint32_t)nb * 8, 2048);  // re-arm next buffer
      mbar_wait_parity(mb_addr + (uint32_t)cb * 8,
                       (uint32_t)(((t >> 1) + (cb ^ 1)) & 1));
    }

    // matvec: 4 outputs per warp, packed f32x2
    unsigned long long c0 = 0ull, c1 = 0ull, c2 = 0ull, c3 = 0ull;
    const float* hb = &hbuf[cb][lane];
#pragma unroll
    for (int m = 0; m < 8; m++) {
      unsigned long long h2 = pk2(hb[64 * m], hb[64 * m + 32]);
      fma2(c0, wp0[m], h2);
      fma2(c1, wp1[m], h2);
      fma2(c2, wp2[m], h2);
      fma2(c3, wp3[m], h2);
    }
    float a0, a1, a2, a3, hi;
    upk2(a0, hi, c0); a0 += hi;
    upk2(a1, hi, c1); a1 += hi;
    upk2(a2, hi, c2); a2 += hi;
    upk2(a3, hi, c3); a3 += hi;
#pragma unroll
    for (int off = 16; off; off >>= 1) {
      a0 += __shfl_xor_sync(0xffffffffu, a0, off);
      a1 += __shfl_xor_sync(0xffffffffu, a1, off);
      a2 += __shfl_xor_sync(0xffffffffu, a2, off);
      a3 += __shfl_xor_sync(0xffffffffu, a3, off);
    }

    if (lane < 4) {
      float y = (lane == 0) ? a0 : (lane == 1) ? a1 : (lane == 2) ? a2 : a3;
      float v = tanhf(y + xsv);
      outp[(size_t)(t * NB + g) * DH + o] = v;
      const uint32_t off32 = (uint32_t)(nb * (DH * 4) + o * 4);
      const uint32_t mboff = mb_delta + (uint32_t)nb * 8;
#pragma unroll
      for (int r = 0; r < 8; r++)
        st_async_f32(peer_hb[r] + off32, v, peer_hb[r] + mboff);
    }
  }

  // don't let any CTA's SMEM die while peers may still be writing into it
  asm volatile("barrier.cluster.arrive.aligned;" ::: "memory");
  asm volatile("barrier.cluster.wait.aligned;" ::: "memory");
}

// ---------------- attention (eos row only) + decoder -------------------------
__global__ __launch_bounds__(256) void attn_kernel(
    const int* __restrict__ eos,
    const float* __restrict__ Wc, const float* __restrict__ bc,
    const float* __restrict__ Wd, const float* __restrict__ bd,
    float* __restrict__ out)
{
  __shared__ float sq[DH];
  __shared__ float sp[LSEQ];
  __shared__ float az[DH];
  __shared__ float sd[DH];
  __shared__ float sred[8];

  const int b    = blockIdx.x;
  const int e    = eos[b];
  const int tid  = threadIdx.x;
  const int lane = tid & 31;
  const int w    = tid >> 5;

  for (int i = tid; i < DH; i += 256) sq[i] = g_O1[(size_t)(e * NB + b) * DH + i];
  __syncthreads();

  for (int s = w; s < LSEQ; s += 8) {
    const float* row = &g_O1[(size_t)(s * NB + b) * DH];
    float acc = 0.0f;
#pragma unroll
    for (int m = 0; m < 4; m++) {
      int k = lane * 4 + 128 * m;
      float4 v = *(const float4*)(row + k);
      acc += v.x * sq[k] + v.y * sq[k + 1] + v.z * sq[k + 2] + v.w * sq[k + 3];
    }
#pragma unroll
    for (int off = 16; off; off >>= 1) acc += __shfl_xor_sync(0xffffffffu, acc, off);
    if (lane == 0) sp[s] = (s < e) ? acc : -1.0e9f;
  }
  __syncthreads();

  float mx = -3.4e38f;
  for (int s = tid; s < LSEQ; s += 256) mx = fmaxf(mx, sp[s]);
#pragma unroll
  for (int off = 16; off; off >>= 1) mx = fmaxf(mx, __shfl_xor_sync(0xffffffffu, mx, off));
  if (lane == 0) sred[w] = mx;
  __syncthreads();
  mx = sred[0];
#pragma unroll
  for (int i = 1; i < 8; i++) mx = fmaxf(mx, sred[i]);
  __syncthreads();

  float ps = 0.0f;
  for (int s = tid; s < LSEQ; s += 256) {
    float e2 = expf(sp[s] - mx);
    sp[s] = e2;
    ps += e2;
  }
#pragma unroll
  for (int off = 16; off; off >>= 1) ps += __shfl_xor_sync(0xffffffffu, ps, off);
  if (lane == 0) sred[w] = ps;
  __syncthreads();
  float S = sred[0];
#pragma unroll
  for (int i = 1; i < 8; i++) S += sred[i];
  const float inv = 1.0f / S;
  __syncthreads();

  for (int h = tid; h < DH; h += 256) {
    float acc = 0.0f;
    const float* col = &g_O1[(size_t)b * DH + h];
#pragma unroll 4
    for (int s = 0; s < LSEQ; s++) acc += sp[s] * col[(size_t)s * NB * DH];
    az[h] = acc * inv;
  }
  __syncthreads();

  for (int j = w; j < DH; j += 8) {
    const float* wr = Wc + (size_t)j * 1024;
    float acc = 0.0f;
#pragma unroll
    for (int m = 0; m < 8; m++) {
      int k = lane * 4 + 128 * m;
      float4 v = *(const float4*)(wr + k);
      const float* src = (m < 4) ? az : sq;
      int kk = (m < 4) ? k : (k - 512);
      acc += v.x * src[kk] + v.y * src[kk + 1] + v.z * src[kk + 2] + v.w * src[kk + 3];
    }
#pragma unroll
    for (int off = 16; off; off >>= 1) acc += __shfl_xor_sync(0xffffffffu, acc, off);
    if (lane == 0) sd[j] = acc + bc[j];
  }
  __syncthreads();

  for (int c = w; c < NCLS; c += 8) {
    const float* wr = Wd + (size_t)c * DH;
    float acc = 0.0f;
#pragma unroll
    for (int m = 0; m < 4; m++) {
      int k = lane * 4 + 128 * m;
      float4 v = *(const float4*)(wr + k);
      acc += v.x * sd[k] + v.y * sd[k + 1] + v.z * sd[k + 2] + v.w * sd[k + 3];
    }
#pragma unroll
    for (int off = 16; off; off >>= 1) acc += __shfl_xor_sync(0xffffffffu, acc, off);
    if (lane == 0) out[b * NCLS + c] = acc + bd[c];
  }
}

// ---------------- host --------------------------------------------------------
static void launch_rnn_cluster(const float* Wh, int layer) {
  cudaLaunchConfig_t cfg = {};
  cfg.gridDim  = dim3(128, 1, 1);
  cfg.blockDim = dim3(512, 1, 1);
  cfg.dynamicSmemBytes = 0;
  cfg.stream = 0;
  cudaLaunchAttribute attrs[1];
  attrs[0].id = cudaLaunchAttributeClusterDimension;
  attrs[0].val.clusterDim.x = 8;
  attrs[0].val.clusterDim.y = 1;
  attrs[0].val.clusterDim.z = 1;
  cfg.attrs = attrs;
  cfg.numAttrs = 1;
  cudaLaunchKernelEx(&cfg, rnn_cluster_kernel, Wh, layer);
}

extern "C" void kernel_launch(void* const* d_in, const int* in_sizes, int n_in,
                              void* d_out, int out_size) {
  const int*   x    = (const int*)  d_in[0];
  const int*   eos  = (const int*)  d_in[1];
  const float* emb  = (const float*)d_in[2];
  const float* W_ih = (const float*)d_in[3];
  const float* W_hh = (const float*)d_in[4];
  const float* b_ih = (const float*)d_in[5];
  const float* b_hh = (const float*)d_in[6];
  const float* Wc   = (const float*)d_in[7];
  const float* bc   = (const float*)d_in[8];
  const float* Wd   = (const float*)d_in[9];
  const float* bd   = (const float*)d_in[10];
  float* out = (float*)d_out;

  dim3 ggrid(NROWS / 128, DH / 128);

  gemm_kernel<<<ggrid, 256>>>(0, x, emb, W_ih, b_ih, b_hh);
  launch_rnn_cluster(W_hh, 0);

  gemm_kernel<<<ggrid, 256>>>(1, x, emb, W_ih + DH * DH, b_ih + DH, b_hh + DH);
  launch_rnn_cluster(W_hh + DH * DH, 1);

  attn_kernel<<<NB, 256>>>(eos, Wc, bc, Wd, bd, out);
}

// round 8
// speedup vs baseline: 1.6499x; 1.0671x over previous
#include <cuda_runtime.h>
#include <cuda_bf16.h>
#include <cstdint>

#define NB    16
#define LSEQ  1024
#define DH    512
#define NCLS  64
#define NROWS (NB * LSEQ)

// ---------------- scratch (static device memory; no allocations) -------------
__device__ float g_XS[NROWS * DH];   // input projection for current layer, rows r = t*16 + b
__device__ float g_O0[NROWS * DH];   // layer-0 outputs
__device__ float g_O1[NROWS * DH];   // layer-1 outputs

// ---------------- small helpers ----------------------------------------------
__device__ __forceinline__ uint32_t s2u(const void* p) {
  uint32_t a;
  asm("{ .reg .u64 t; cvta.to.shared.u64 t, %1; cvt.u32.u64 %0, t; }" : "=r"(a) : "l"(p));
  return a;
}
__device__ __forceinline__ unsigned long long pk2(float lo, float hi) {
  unsigned long long r;
  asm("mov.b64 %0, {%1, %2};" : "=l"(r) : "f"(lo), "f"(hi));
  return r;
}
__device__ __forceinline__ void upk2(float& lo, float& hi, unsigned long long v) {
  asm("mov.b64 {%0, %1}, %2;" : "=f"(lo), "=f"(hi) : "l"(v));
}
__device__ __forceinline__ void fma2(unsigned long long& d, unsigned long long a,
                                     unsigned long long b) {
  asm("fma.rn.f32x2 %0, %1, %2, %0;" : "+l"(d) : "l"(a), "l"(b));
}
__device__ __forceinline__ void mbar_init(uint32_t mbar, uint32_t cnt) {
  asm volatile("mbarrier.init.shared.b64 [%0], %1;" :: "r"(mbar), "r"(cnt) : "memory");
}
__device__ __forceinline__ void mbar_expect_tx(uint32_t mbar, uint32_t bytes) {
  asm volatile("mbarrier.arrive.expect_tx.shared.b64 _, [%0], %1;"
               :: "r"(mbar), "r"(bytes) : "memory");
}
__device__ __forceinline__ void mbar_wait_parity(uint32_t mbar, uint32_t parity) {
  asm volatile(
      "{\n\t.reg .pred P1;\n\t"
      "WAIT_LOOP_%=:\n\t"
      "mbarrier.try_wait.parity.acquire.cta.shared::cta.b64 P1, [%0], %1, 0x989680;\n\t"
      "@P1 bra.uni WAIT_DONE_%=;\n\t"
      "bra.uni WAIT_LOOP_%=;\n\t"
      "WAIT_DONE_%=:\n\t}"
      :: "r"(mbar), "r"(parity) : "memory");
}
__device__ __forceinline__ uint32_t mapa_u32(uint32_t addr, uint32_t rank) {
  uint32_t r;
  asm("mapa.shared::cluster.u32 %0, %1, %2;" : "=r"(r) : "r"(addr), "r"(rank));
  return r;
}
__device__ __forceinline__ void st_async_v4(uint32_t dst, float f0, float f1,
                                            float f2, float f3, uint32_t mbar) {
  asm volatile(
      "st.async.shared::cluster.mbarrier::complete_tx::bytes.v4.b32 "
      "[%0], {%1, %2, %3, %4}, [%5];"
      :: "r"(dst), "r"(__float_as_uint(f0)), "r"(__float_as_uint(f1)),
         "r"(__float_as_uint(f2)), "r"(__float_as_uint(f3)), "r"(mbar)
      : "memory");
}

// ---------------- GEMM: g_XS = A @ W^T + bias1 + bias2 -----------------------
// mode 0: A row r = emb[x[b][t]]   (r = t*16 + b);   mode 1: A row r = g_O0[r]
// Tile 128x128, K-chunk 16, 8x8 microtile (256 threads), f32x2 packed FMA.
__global__ __launch_bounds__(256) void gemm_kernel(
    int mode, const int* __restrict__ xtok, const float* __restrict__ emb,
    const float* __restrict__ W, const float* __restrict__ bias1,
    const float* __restrict__ bias2)
{
  __shared__ __align__(16) float As[16][132];
  __shared__ __align__(16) float Bs[16][132];
  const int r0  = blockIdx.x * 128;
  const int h0  = blockIdx.y * 128;
  const int tid = threadIdx.x;
  const int tr  = (tid & 15) * 8;
  const int tc  = (tid >> 4) * 8;

  unsigned long long acc2[8][4];
#pragma unroll
  for (int i = 0; i < 8; i++)
#pragma unroll
    for (int j = 0; j < 4; j++) acc2[i][j] = 0ull;

  for (int kk = 0; kk < DH; kk += 16) {
#pragma unroll
    for (int it = 0; it < 2; it++) {
      int idx = tid + it * 256;        // 0..511
      int i = idx >> 2;                // row within tile 0..127
      int q = idx & 3;                 // k-quad
      const float* arow;
      if (mode == 0) {
        int r = r0 + i;
        int tok = xtok[(r & 15) * LSEQ + (r >> 4)];
        arow = emb + (size_t)tok * DH;
      } else {
        arow = g_O0 + (size_t)(r0 + i) * DH;
      }
      float4 va = *(const float4*)(arow + kk + q * 4);
      As[q * 4 + 0][i] = va.x; As[q * 4 + 1][i] = va.y;
      As[q * 4 + 2][i] = va.z; As[q * 4 + 3][i] = va.w;
      float4 vb = *(const float4*)(W + (size_t)(h0 + i) * DH + kk + q * 4);
      Bs[q * 4 + 0][i] = vb.x; Bs[q * 4 + 1][i] = vb.y;
      Bs[q * 4 + 2][i] = vb.z; Bs[q * 4 + 3][i] = vb.w;
    }
    __syncthreads();
#pragma unroll
    for (int k = 0; k < 16; k++) {
      float a[8];
      *(float4*)&a[0] = *(const float4*)&As[k][tr];
      *(float4*)&a[4] = *(const float4*)&As[k][tr + 4];
      const unsigned long long* brow = (const unsigned long long*)&Bs[k][tc];
      unsigned long long b2[4];
#pragma unroll
      for (int j = 0; j < 4; j++) b2[j] = brow[j];
#pragma unroll
      for (int i = 0; i < 8; i++) {
        unsigned long long a2 = pk2(a[i], a[i]);
#pragma unroll
        for (int j = 0; j < 4; j++) fma2(acc2[i][j], a2, b2[j]);
      }
    }
    __syncthreads();
  }

  float bs[8];
#pragma unroll
  for (int j = 0; j < 8; j++) bs[j] = bias1[h0 + tc + j] + bias2[h0 + tc + j];
#pragma unroll
  for (int i = 0; i < 8; i++) {
    float* crow = g_XS + (size_t)(r0 + tr + i) * DH + h0 + tc;
#pragma unroll
    for (int j = 0; j < 4; j++) {
      float lo, hi;
      upk2(lo, hi, acc2[i][j]);
      crow[2 * j]     = lo + bs[2 * j];
      crow[2 * j + 1] = hi + bs[2 * j + 1];
    }
  }
}

// ---------------- recurrence: 16 clusters of 8 CTAs, DSMEM h-exchange ---------
// Cluster = one batch element. CTA rank owns 64 output dims; Wh slice packed
// f32x2 register-resident (contiguous dim-pairs). h exchanged via 16-byte
// st.async.v4 into all 8 CTAs' SMEM (128 msgs/CTA/step), double-buffered
// mbarriers with expect_tx = 2048 B per phase.
__global__ void __launch_bounds__(512, 1) rnn_cluster_kernel(
    const float* __restrict__ Wh, int layer)
{
  __shared__ __align__(16) float hbuf[2][DH];
  __shared__ __align__(8) unsigned long long mbar[2];

  const int g    = blockIdx.x >> 3;
  const int tid  = threadIdx.x;
  const int lane = tid & 31;
  const int w    = tid >> 5;                 // 0..15
  uint32_t rank;
  asm("mov.u32 %0, %%cluster_ctarank;" : "=r"(rank));
  const int co = (int)rank * 64;
  float* outp = layer ? g_O1 : g_O0;

  const uint32_t hb_addr  = s2u(&hbuf[0][0]);
  const uint32_t mb_addr  = s2u(&mbar[0]);
  const uint32_t mb_delta = mb_addr - hb_addr;

  // packed weight slice: outputs o_j = co+4w+j; lane covers dim pairs
  // {2*lane + 64m, 2*lane + 64m + 1}, m = 0..7  (conflict-free LDS.64 on h)
  unsigned long long wp0[8], wp1[8], wp2[8], wp3[8];
  {
    const float* wr0 = Wh + (size_t)(co + w * 4 + 0) * DH + 2 * lane;
    const float* wr1 = Wh + (size_t)(co + w * 4 + 1) * DH + 2 * lane;
    const float* wr2 = Wh + (size_t)(co + w * 4 + 2) * DH + 2 * lane;
    const float* wr3 = Wh + (size_t)(co + w * 4 + 3) * DH + 2 * lane;
#pragma unroll
    for (int m = 0; m < 8; m++) {
      wp0[m] = pk2(wr0[64 * m], wr0[64 * m + 1]);
      wp1[m] = pk2(wr1[64 * m], wr1[64 * m + 1]);
      wp2[m] = pk2(wr2[64 * m], wr2[64 * m + 1]);
      wp3[m] = pk2(wr3[64 * m], wr3[64 * m + 1]);
    }
  }

  // one peer SMEM base per lane (lanes 0..7 are the senders, rank = lane)
  const uint32_t my_peer = mapa_u32(hb_addr, (uint32_t)(lane & 7));

  if (tid == 0) {
    mbar_init(mb_addr, 1);
    mbar_init(mb_addr + 8, 1);
    mbar_expect_tx(mb_addr + 8, 2048);       // arm buffer 1 for step-0 exchange
  }
  for (int i = tid; i < DH; i += 512) hbuf[0][i] = 0.0f;   // h_{-1} = 0
  asm volatile("barrier.cluster.arrive.aligned;" ::: "memory");
  asm volatile("barrier.cluster.wait.aligned;" ::: "memory");

  const int ob = co + w * 4;                 // warp's first output dim

#pragma unroll 1
  for (int t = 0; t < LSEQ; t++) {
    const int cb = t & 1, nb = cb ^ 1;

    // prefetch xs (independent of h_{t-1}) before blocking; broadcast LDG.128
    const float4 xq = *(const float4*)&g_XS[(size_t)(t * NB + g) * DH + ob];

    if (t > 0) {
      if (tid == 0) mbar_expect_tx(mb_addr + (uint32_t)nb * 8, 2048);  // re-arm
      mbar_wait_parity(mb_addr + (uint32_t)cb * 8,
                       (uint32_t)(((t >> 1) + (cb ^ 1)) & 1));
    }

    // matvec: 4 outputs per warp, packed f32x2, contiguous h pairs
    unsigned long long c0 = 0ull, c1 = 0ull, c2 = 0ull, c3 = 0ull;
    const unsigned long long* hb =
        (const unsigned long long*)&hbuf[cb][2 * lane];
#pragma unroll
    for (int m = 0; m < 8; m++) {
      unsigned long long h2 = hb[32 * m];    // = hbuf[cb][2*lane + 64m .. +1]
      fma2(c0, wp0[m], h2);
      fma2(c1, wp1[m], h2);
      fma2(c2, wp2[m], h2);
      fma2(c3, wp3[m], h2);
    }
    float a0, a1, a2, a3, hi;
    upk2(a0, hi, c0); a0 += hi;
    upk2(a1, hi, c1); a1 += hi;
    upk2(a2, hi, c2); a2 += hi;
    upk2(a3, hi, c3); a3 += hi;
#pragma unroll
    for (int off = 16; off; off >>= 1) {
      a0 += __shfl_xor_sync(0xffffffffu, a0, off);
      a1 += __shfl_xor_sync(0xffffffffu, a1, off);
      a2 += __shfl_xor_sync(0xffffffffu, a2, off);
      a3 += __shfl_xor_sync(0xffffffffu, a3, off);
    }

    // lane j (j<4) computes output j of this warp (single tanhf stream/warp)
    float aj = (lane == 0) ? a0 : (lane == 1) ? a1 : (lane == 2) ? a2 : a3;
    float xj = (lane == 0) ? xq.x : (lane == 1) ? xq.y : (lane == 2) ? xq.z : xq.w;
    float v  = tanhf(aj + xj);

    // gather the 4 outputs into every lane (independent shuffles)
    float f0 = __shfl_sync(0xffffffffu, v, 0);
    float f1 = __shfl_sync(0xffffffffu, v, 1);
    float f2 = __shfl_sync(0xffffffffu, v, 2);
    float f3 = __shfl_sync(0xffffffffu, v, 3);

    const uint32_t off16 = (uint32_t)(nb * (DH * 4) + ob * 4);
    if (lane < 8) {
      // one 16B async store per rank (rank = lane)
      st_async_v4(my_peer + off16, f0, f1, f2, f3,
                  my_peer + mb_delta + (uint32_t)nb * 8);
    } else if (lane == 8) {
      *(float4*)&outp[(size_t)(t * NB + g) * DH + ob] =
          make_float4(f0, f1, f2, f3);
    }
  }

  // don't let any CTA's SMEM die while peers may still be writing into it
  asm volatile("barrier.cluster.arrive.aligned;" ::: "memory");
  asm volatile("barrier.cluster.wait.aligned;" ::: "memory");
}

// ---------------- attention (eos row only) + decoder -------------------------
__global__ __launch_bounds__(256) void attn_kernel(
    const int* __restrict__ eos,
    const float* __restrict__ Wc, const float* __restrict__ bc,
    const float* __restrict__ Wd, const float* __restrict__ bd,
    float* __restrict__ out)
{
  __shared__ float sq[DH];
  __shared__ float sp[LSEQ];
  __shared__ float az[DH];
  __shared__ float sd[DH];
  __shared__ float sred[8];

  const int b    = blockIdx.x;
  const int e    = eos[b];
  const int tid  = threadIdx.x;
  const int lane = tid & 31;
  const int w    = tid >> 5;

  for (int i = tid; i < DH; i += 256) sq[i] = g_O1[(size_t)(e * NB + b) * DH + i];
  __syncthreads();

  for (int s = w; s < LSEQ; s += 8) {
    const float* row = &g_O1[(size_t)(s * NB + b) * DH];
    float acc = 0.0f;
#pragma unroll
    for (int m = 0; m < 4; m++) {
      int k = lane * 4 + 128 * m;
      float4 v = *(const float4*)(row + k);
      acc += v.x * sq[k] + v.y * sq[k + 1] + v.z * sq[k + 2] + v.w * sq[k + 3];
    }
#pragma unroll
    for (int off = 16; off; off >>= 1) acc += __shfl_xor_sync(0xffffffffu, acc, off);
    if (lane == 0) sp[s] = (s < e) ? acc : -1.0e9f;
  }
  __syncthreads();

  float mx = -3.4e38f;
  for (int s = tid; s < LSEQ; s += 256) mx = fmaxf(mx, sp[s]);
#pragma unroll
  for (int off = 16; off; off >>= 1) mx = fmaxf(mx, __shfl_xor_sync(0xffffffffu, mx, off));
  if (lane == 0) sred[w] = mx;
  __syncthreads();
  mx = sred[0];
#pragma unroll
  for (int i = 1; i < 8; i++) mx = fmaxf(mx, sred[i]);
  __syncthreads();

  float ps = 0.0f;
  for (int s = tid; s < LSEQ; s += 256) {
    float e2 = expf(sp[s] - mx);
    sp[s] = e2;
    ps += e2;
  }
#pragma unroll
  for (int off = 16; off; off >>= 1) ps += __shfl_xor_sync(0xffffffffu, ps, off);
  if (lane == 0) sred[w] = ps;
  __syncthreads();
  float S = sred[0];
#pragma unroll
  for (int i = 1; i < 8; i++) S += sred[i];
  const float inv = 1.0f / S;
  __syncthreads();

  for (int h = tid; h < DH; h += 256) {
    float acc = 0.0f;
    const float* col = &g_O1[(size_t)b * DH + h];
#pragma unroll 4
    for (int s = 0; s < LSEQ; s++) acc += sp[s] * col[(size_t)s * NB * DH];
    az[h] = acc * inv;
  }
  __syncthreads();

  for (int j = w; j < DH; j += 8) {
    const float* wr = Wc + (size_t)j * 1024;
    float acc = 0.0f;
#pragma unroll
    for (int m = 0; m < 8; m++) {
      int k = lane * 4 + 128 * m;
      float4 v = *(const float4*)(wr + k);
      const float* src = (m < 4) ? az : sq;
      int kk = (m < 4) ? k : (k - 512);
      acc += v.x * src[kk] + v.y * src[kk + 1] + v.z * src[kk + 2] + v.w * src[kk + 3];
    }
#pragma unroll
    for (int off = 16; off; off >>= 1) acc += __shfl_xor_sync(0xffffffffu, acc, off);
    if (lane == 0) sd[j] = acc + bc[j];
  }
  __syncthreads();

  for (int c = w; c < NCLS; c += 8) {
    const float* wr = Wd + (size_t)c * DH;
    float acc = 0.0f;
#pragma unroll
    for (int m = 0; m < 4; m++) {
      int k = lane * 4 + 128 * m;
      float4 v = *(const float4*)(wr + k);
      acc += v.x * sd[k] + v.y * sd[k + 1] + v.z * sd[k + 2] + v.w * sd[k + 3];
    }
#pragma unroll
    for (int off = 16; off; off >>= 1) acc += __shfl_xor_sync(0xffffffffu, acc, off);
    if (lane == 0) out[b * NCLS + c] = acc + bd[c];
  }
}

// ---------------- host --------------------------------------------------------
static void launch_rnn_cluster(const float* Wh, int layer) {
  cudaLaunchConfig_t cfg = {};
  cfg.gridDim  = dim3(128, 1, 1);
  cfg.blockDim = dim3(512, 1, 1);
  cfg.dynamicSmemBytes = 0;
  cfg.stream = 0;
  cudaLaunchAttribute attrs[1];
  attrs[0].id = cudaLaunchAttributeClusterDimension;
  attrs[0].val.clusterDim.x = 8;
  attrs[0].val.clusterDim.y = 1;
  attrs[0].val.clusterDim.z = 1;
  cfg.attrs = attrs;
  cfg.numAttrs = 1;
  cudaLaunchKernelEx(&cfg, rnn_cluster_kernel, Wh, layer);
}

extern "C" void kernel_launch(void* const* d_in, const int* in_sizes, int n_in,
                              void* d_out, int out_size) {
  const int*   x    = (const int*)  d_in[0];
  const int*   eos  = (const int*)  d_in[1];
  const float* emb  = (const float*)d_in[2];
  const float* W_ih = (const float*)d_in[3];
  const float* W_hh = (const float*)d_in[4];
  const float* b_ih = (const float*)d_in[5];
  const float* b_hh = (const float*)d_in[6];
  const float* Wc   = (const float*)d_in[7];
  const float* bc   = (const float*)d_in[8];
  const float* Wd   = (const float*)d_in[9];
  const float* bd   = (const float*)d_in[10];
  float* out = (float*)d_out;

  dim3 ggrid(NROWS / 128, DH / 128);

  gemm_kernel<<<ggrid, 256>>>(0, x, emb, W_ih, b_ih, b_hh);
  launch_rnn_cluster(W_hh, 0);

  gemm_kernel<<<ggrid, 256>>>(1, x, emb, W_ih + DH * DH, b_ih + DH, b_hh + DH);
  launch_rnn_cluster(W_hh + DH * DH, 1);

  attn_kernel<<<NB, 256>>>(eos, Wc, bc, Wd, bd, out);
}